// round 12
// baseline (speedup 1.0000x reference)
#include <cuda_runtime.h>
#include <cuda_fp16.h>

typedef unsigned int u32;

#define H 512
#define W 512
#define PLANE (H * W)
#define NPLANES 64          // 32 pred + 32 true planes (channel 1 only)
#define RB 8                // output rows per warp
#define BANDS (H / RB)      // 64
#define KSTEPS (RB + 4)     // 12 pipeline steps
#define NBLOCKS (NPLANES * BANDS * 2 / 4)   // 2048 blocks of 128 thr
#define SROW 132            // u32 per staged row: [0..127]=data [128]=Lhalo [129]=Rhalo

#define PINF2 0x7C007C00u
#define NINF2 0xFC00FC00u

__device__ __half g_bufA[(size_t)NPLANES * PLANE];   // 32 MB
__device__ __half g_bufB[(size_t)NPLANES * PLANE];   // 32 MB
__device__ double g_acc[4];  // cross_pred, sum_pred, cross_true, sum_true

__device__ __forceinline__ u32 h2min(u32 a, u32 b) {
    __half2 r = __hmin2(*reinterpret_cast<__half2*>(&a),
                        *reinterpret_cast<__half2*>(&b));
    return *reinterpret_cast<u32*>(&r);
}
__device__ __forceinline__ u32 h2max(u32 a, u32 b) {
    __half2 r = __hmax2(*reinterpret_cast<__half2*>(&a),
                        *reinterpret_cast<__half2*>(&b));
    return *reinterpret_cast<u32*>(&r);
}
__device__ __forceinline__ u32 h2sub(u32 a, u32 b) {
    __half2 r = __hsub2(*reinterpret_cast<__half2*>(&a),
                        *reinterpret_cast<__half2*>(&b));
    return *reinterpret_cast<u32*>(&r);
}
__device__ __forceinline__ u32 h2add(u32 a, u32 b) {
    __half2 r = __hadd2(*reinterpret_cast<__half2*>(&a),
                        *reinterpret_cast<__half2*>(&b));
    return *reinterpret_cast<u32*>(&r);
}
__device__ __forceinline__ u32 pk(float lo, float hi) {
    __half2 r = __floats2half2_rn(lo, hi);
    return *reinterpret_cast<u32*>(&r);
}
__device__ __forceinline__ float2 up(u32 v) {
    return __half22float2(*reinterpret_cast<__half2*>(&v));
}
__device__ __forceinline__ u32 mid(u32 a, u32 b) { return __byte_perm(a, b, 0x5432); }
__device__ __forceinline__ u32 swp(u32 a)        { return __byte_perm(a, a, 0x1032); }

// =====================================================================
// Pipeline step (operates on xn[6] = 12 cols: halo +-2 around 8 owned):
// vmin pair -> hmin -> (EDGE row pad) -> hmax -> vmax pair -> z.
// =====================================================================
struct PipeState {
    u32 xprev[6], xpair[6];
    u32 xc1[4], xc2[4], mcp[4];
    u32 hmp[4], hmpair[4];
    __device__ __forceinline__ void init() {
#pragma unroll
        for (int i = 0; i < 6; ++i) { xprev[i] = PINF2; xpair[i] = PINF2; }
#pragma unroll
        for (int i = 0; i < 4; ++i) {
            xc1[i] = 0u; xc2[i] = 0u; mcp[i] = 0u;
            hmp[i] = NINF2; hmpair[i] = NINF2;
        }
    }
};

template <bool EDGE>
__device__ __forceinline__ void pipe_step(
    PipeState& st, const u32 xn[6], int rv, u32 z[4], bool emit)
{
    u32 v[6];
#pragma unroll
    for (int i = 0; i < 6; ++i) v[i] = h2min(st.xpair[i], xn[i]);
#pragma unroll
    for (int i = 0; i < 6; ++i) { st.xpair[i] = h2min(st.xprev[i], xn[i]); st.xprev[i] = xn[i]; }

    u32 p01 = mid(v[0], v[1]), p12 = mid(v[1], v[2]), p23 = mid(v[2], v[3]);
    u32 p34 = mid(v[3], v[4]), p45 = mid(v[4], v[5]);
    u32 m0 = h2min(h2min(swp(v[0]), v[0]), p01);
    u32 m1 = h2min(h2min(p01, v[1]), p12);
    u32 m2 = h2min(h2min(p12, v[2]), p23);
    u32 m3 = h2min(h2min(p23, v[3]), p34);
    u32 m4 = h2min(h2min(p34, v[4]), p45);
    u32 m5 = h2min(h2min(p45, v[5]), swp(v[5]));

    if (EDGE && (unsigned)rv >= H) {     // maxpool pads -inf for OOB rows
        m0 = m1 = m2 = m3 = m4 = m5 = NINF2;
    }

    u32 q01 = mid(m0, m1), q12 = mid(m1, m2), q23 = mid(m2, m3);
    u32 q34 = mid(m3, m4), q45 = mid(m4, m5);
    u32 hv0 = h2max(h2max(q01, m1), q12);
    u32 hv1 = h2max(h2max(q12, m2), q23);
    u32 hv2 = h2max(h2max(q23, m3), q34);
    u32 hv3 = h2max(h2max(q34, m4), q45);

    if (emit) {
        // z = relu(x_o - dil + m_o), dil = max(hmpair, hv)  (dil >= m always)
        z[0] = h2max(h2add(h2sub(st.xc2[0], h2max(st.hmpair[0], hv0)), st.mcp[0]), 0u);
        z[1] = h2max(h2add(h2sub(st.xc2[1], h2max(st.hmpair[1], hv1)), st.mcp[1]), 0u);
        z[2] = h2max(h2add(h2sub(st.xc2[2], h2max(st.hmpair[2], hv2)), st.mcp[2]), 0u);
        z[3] = h2max(h2add(h2sub(st.xc2[3], h2max(st.hmpair[3], hv3)), st.mcp[3]), 0u);
    }

    st.hmpair[0] = h2max(st.hmp[0], hv0); st.hmp[0] = hv0;
    st.hmpair[1] = h2max(st.hmp[1], hv1); st.hmp[1] = hv1;
    st.hmpair[2] = h2max(st.hmp[2], hv2); st.hmp[2] = hv2;
    st.hmpair[3] = h2max(st.hmp[3], hv3); st.hmp[3] = hv3;
    st.mcp[0] = m1; st.mcp[1] = m2; st.mcp[2] = m3; st.mcp[3] = m4;
#pragma unroll
    for (int i = 0; i < 4; ++i) { st.xc2[i] = st.xc1[i]; st.xc1[i] = xn[i + 1]; }
}

// =====================================================================
// MODE 0: fp32 strided input, register raw-ring + shuffles.
// =====================================================================
template <bool EDGE>
__device__ __forceinline__ void reg_core0(
    int lane, int rbase, int cb, bool eL, bool eR,
    const float* __restrict__ chan, __half* __restrict__ dstH)
{
    u32 raw[4][4];
    u32 rawE[4];
    PipeState st; st.init();

    auto loadraw = [&](int r, int s) {
        u32 a1 = PINF2, a2 = PINF2, a3 = PINF2, a4 = PINF2, ae = PINF2;
        if (!EDGE || (unsigned)r < H) {
            const float* row = chan + (size_t)r * W + cb;
            float4 f0 = *reinterpret_cast<const float4*>(row);
            float4 f1 = *reinterpret_cast<const float4*>(row + 4);
            a1 = pk(f0.x, f0.y); a2 = pk(f0.z, f0.w);
            a3 = pk(f1.x, f1.y); a4 = pk(f1.z, f1.w);
            if (eL)      { float2 e = *reinterpret_cast<const float2*>(row - 2); ae = pk(e.x, e.y); }
            else if (eR) { float2 e = *reinterpret_cast<const float2*>(row + 8); ae = pk(e.x, e.y); }
        }
        raw[s][0] = a1; raw[s][1] = a2; raw[s][2] = a3; raw[s][3] = a4;
        rawE[s] = ae;
    };

    loadraw(rbase - 2, 0);
    loadraw(rbase - 1, 1);

#pragma unroll
    for (int k = 0; k < KSTEPS; ++k) {
        if (k < KSTEPS - 2) loadraw(rbase + k, (k + 2) & 3);

        u32 xn[6];
        {
            const int s = k & 3;
            u32 a1 = raw[s][0], a4 = raw[s][3];
            u32 a0 = __shfl_up_sync(0xffffffffu, a4, 1);
            u32 a5 = __shfl_down_sync(0xffffffffu, a1, 1);
            if (lane == 0)  a0 = eL ? rawE[s] : PINF2;
            if (lane == 31) a5 = eR ? rawE[s] : PINF2;
            xn[0] = a0; xn[1] = a1; xn[2] = raw[s][1];
            xn[3] = raw[s][2]; xn[4] = a4; xn[5] = a5;
        }

        u32 z[4];
        pipe_step<EDGE>(st, xn, rbase + k - 3, z, k >= 4);
        if (k >= 4) {
            const int o = rbase + k - 4;
            uint4 s4; s4.x = z[0]; s4.y = z[1]; s4.z = z[2]; s4.w = z[3];
            *reinterpret_cast<uint4*>(dstH + (size_t)o * W + cb) = s4;
        }
    }
}

// =====================================================================
// MODE 1/2: half input staged through per-warp smem ring via cp.async.
// Each lane reads ONLY its own staged bytes (1 aligned uint4 LDS; strip
// edge = 1 predicated single-lane LDS); lane-halo comes from 2 shuffles
// on the LDS'd registers. Consume is double-buffered one step ahead, so
// LDS+SHFL latency hides under a full compute body. No conflicted scalar
// LDS, no per-step syncwarp (all smem reads are lane-self-owned).
// =====================================================================
template <int MODE, bool EDGE>
__device__ __forceinline__ void smem_core(
    u32* __restrict__ swm, int lane, int rbase, int cb, bool eL, bool eR,
    const __half* __restrict__ srcH, __half* __restrict__ dstH,
    const float* __restrict__ oth, float& accC_, float& accS_)
{
    const u32 swa = (u32)__cvta_generic_to_shared(swm);
    PipeState st; st.init();
    float accC = 0.f, accS = 0.f;

    // slot j holds row rbase-2+j (mod 6)
    auto issue = [&](int j) {
        const int r = rbase - 2 + j;
        const int s = j % 6;
        const u32 sbase = swa + (u32)(s * SROW) * 4u;
        if (!EDGE || (unsigned)r < H) {
            const __half* row = srcH + (size_t)r * W + cb;
            asm volatile("cp.async.cg.shared.global [%0], [%1], 16;\n"
                         :: "r"(sbase + 16u * (u32)lane), "l"(row));
            if (eL) {
                asm volatile("cp.async.ca.shared.global [%0], [%1], 4;\n"
                             :: "r"(sbase + 128u * 4u), "l"(row - 2));
            } else if (eR) {
                asm volatile("cp.async.ca.shared.global [%0], [%1], 4;\n"
                             :: "r"(sbase + 129u * 4u), "l"(row + 8));
            }
        } else {
            *reinterpret_cast<uint4*>(swm + s * SROW + 4 * lane) =
                make_uint4(PINF2, PINF2, PINF2, PINF2);
            if (eL) swm[s * SROW + 128] = PINF2;
            if (eR) swm[s * SROW + 129] = PINF2;
        }
        asm volatile("cp.async.commit_group;\n" ::);
    };

    // LDS own uint4 (+ 1-lane edge word), then expand lane-halo by shuffle.
    auto consume = [&](int j, u32 xn[6]) {
        const u32* sb = swm + (j % 6) * SROW;
        uint4 c = *reinterpret_cast<const uint4*>(sb + 4 * lane);
        u32 ed = PINF2;
        if (eL) ed = sb[128];
        else if (eR) ed = sb[129];
        u32 a0 = __shfl_up_sync(0xffffffffu, c.w, 1);
        u32 a5 = __shfl_down_sync(0xffffffffu, c.x, 1);
        if (lane == 0)  a0 = eL ? ed : PINF2;
        if (lane == 31) a5 = eR ? ed : PINF2;
        xn[0] = a0; xn[1] = c.x; xn[2] = c.y;
        xn[3] = c.z; xn[4] = c.w; xn[5] = a5;
    };

    issue(0); issue(1); issue(2); issue(3);      // rows rbase-2 .. rbase+1
    asm volatile("cp.async.wait_group 3;\n" ::); // slot 0 landed
    u32 xn[6];
    consume(0, xn);

#pragma unroll
    for (int k = 0; k < KSTEPS; ++k) {
        // issue slot k+4 (depth-3 in flight); keep one group per step
        if (k + 4 < KSTEPS) issue(k + 4);
        else asm volatile("cp.async.commit_group;\n" ::);
        asm volatile("cp.async.wait_group 3;\n" ::);   // slot k+1 landed

        u32 xn2[6];
        if (k + 1 < KSTEPS) consume(k + 1, xn2);   // prefetch next row

        u32 z[4];
        pipe_step<EDGE>(st, xn, rbase + k - 3, z, k >= 4);

        if (k >= 4) {
            const int o = rbase + k - 4;
            if (MODE == 2) {
                const float* orow = oth + (size_t)o * W + cb;
                float4 f0 = *reinterpret_cast<const float4*>(orow);
                float4 f1 = *reinterpret_cast<const float4*>(orow + 4);
                float2 a0 = up(z[0]), a1 = up(z[1]), a2 = up(z[2]), a3 = up(z[3]);
                accC += a0.x * f0.x + a0.y * f0.y + a1.x * f0.z + a1.y * f0.w;
                accC += a2.x * f1.x + a2.y * f1.y + a3.x * f1.z + a3.y * f1.w;
                accS += (a0.x + a0.y) + (a1.x + a1.y)
                      + (a2.x + a2.y) + (a3.x + a3.y);
            } else {
                uint4 s4; s4.x = z[0]; s4.y = z[1]; s4.z = z[2]; s4.w = z[3];
                *reinterpret_cast<uint4*>(dstH + (size_t)o * W + cb) = s4;
            }
        }

        if (k + 1 < KSTEPS) {
#pragma unroll
            for (int i = 0; i < 6; ++i) xn[i] = xn2[i];
        }
    }

    accC_ = accC;
    accS_ = accS;
}

// =====================================================================
// Kernels
// =====================================================================
__global__ void __launch_bounds__(128) skel0_kernel(
    const float* __restrict__ pred, const float* __restrict__ tru)
{
    // fold accumulator zeroing into iteration 0 (read by MODE2 much later)
    if (blockIdx.x == 0 && threadIdx.x < 4) g_acc[threadIdx.x] = 0.0;

    const int lane  = threadIdx.x & 31;
    const int gw    = blockIdx.x * 4 + (threadIdx.x >> 5);
    const int strip = gw & 1;
    const int band  = (gw >> 1) & (BANDS - 1);
    const int p     = gw >> 7;
    const int rbase = band * RB;
    const int cb    = strip * 256 + lane * 8;
    const int b     = p & 31;

    const float* chan = (p < 32 ? pred : tru) + (size_t)(2 * b + 1) * PLANE;
    __half* dstH = g_bufA + (size_t)p * PLANE;   // it 0 writes bufA

    const bool eL = (lane == 0  && strip == 1);
    const bool eR = (lane == 31 && strip == 0);

    if (band == 0 || band == BANDS - 1)
        reg_core0<true >(lane, rbase, cb, eL, eR, chan, dstH);
    else
        reg_core0<false>(lane, rbase, cb, eL, eR, chan, dstH);
}

template <int MODE>
__global__ void __launch_bounds__(128, 9) skel_kernel(
    const float* __restrict__ pred, const float* __restrict__ tru, int it)
{
    __shared__ __align__(16) u32 stg[4][6 * SROW];   // ~12.7 KB / block

    const int lane  = threadIdx.x & 31;
    const int wi    = threadIdx.x >> 5;
    const int gw    = blockIdx.x * 4 + wi;
    const int strip = gw & 1;
    const int band  = (gw >> 1) & (BANDS - 1);
    const int p     = gw >> 7;
    const int rbase = band * RB;
    const int cb    = strip * 256 + lane * 8;
    const int b     = p & 31;

    const float* oth  = (p < 32 ? tru : pred) + (size_t)(2 * b + 1) * PLANE;
    const size_t off  = (size_t)p * PLANE;
    const __half* srcH; __half* dstH;
    if (it & 1) { srcH = g_bufA + off; dstH = g_bufB + off; }
    else        { srcH = g_bufB + off; dstH = g_bufA + off; }

    const bool eL = (lane == 0  && strip == 1);
    const bool eR = (lane == 31 && strip == 0);

    float accC = 0.f, accS = 0.f;
    if (band == 0 || band == BANDS - 1)
        smem_core<MODE, true >(stg[wi], lane, rbase, cb, eL, eR, srcH, dstH, oth, accC, accS);
    else
        smem_core<MODE, false>(stg[wi], lane, rbase, cb, eL, eR, srcH, dstH, oth, accC, accS);

    if (MODE == 2) {
#pragma unroll
        for (int s = 16; s; s >>= 1) {
            accC += __shfl_xor_sync(0xffffffffu, accC, s);
            accS += __shfl_xor_sync(0xffffffffu, accS, s);
        }
        __shared__ float sC[4], sS[4];
        if (lane == 0) { sC[wi] = accC; sS[wi] = accS; }
        __syncthreads();
        if (threadIdx.x == 0) {
            double c = (double)sC[0] + sC[1] + sC[2] + sC[3];
            double s = (double)sS[0] + sS[1] + sS[2] + sS[3];
            const int base = (p < 32) ? 0 : 2;   // p constant within block
            atomicAdd(&g_acc[base],     c);
            atomicAdd(&g_acc[base + 1], s);
        }
    }
}

__global__ void finalize_kernel(float* out)
{
    const double SMOOTH = 1.0;
    double tprec = (g_acc[0] + SMOOTH) / (g_acc[1] + SMOOTH);
    double tsens = (g_acc[2] + SMOOTH) / (g_acc[3] + SMOOTH);
    out[0] = (float)(1.0 - 2.0 * (tprec * tsens) / (tprec + tsens));
}

extern "C" void kernel_launch(void* const* d_in, const int* in_sizes, int n_in,
                              void* d_out, int out_size)
{
    const float* pred = (const float*)d_in[0];
    const float* tru  = (const float*)d_in[1];

    skel0_kernel<<<NBLOCKS, 128>>>(pred, tru);             // it 0 -> bufA (+acc zero)
    for (int it = 1; it < 9; ++it)
        skel_kernel<1><<<NBLOCKS, 128>>>(pred, tru, it);   // ping-pong
    skel_kernel<2><<<NBLOCKS, 128>>>(pred, tru, 9);        // + reduction
    finalize_kernel<<<1, 1>>>((float*)d_out);
}

// round 13
// speedup vs baseline: 1.0855x; 1.0855x over previous
#include <cuda_runtime.h>
#include <cuda_fp16.h>

typedef unsigned int u32;

#define H 512
#define W 512
#define PLANE (H * W)
#define NPLANES 64          // 32 pred + 32 true planes (channel 1 only)

// smem-staged skeleton kernels (9 launches)
#define RB_S 16
#define BANDS_S (H / RB_S)      // 32
#define KSTEPS_S (RB_S + 4)     // 20
#define NBLOCKS_S (NPLANES * BANDS_S * 2 / 4)   // 1024

// iteration-0 kernel (fp32 strided input, register pipeline)
#define RB_R 8
#define BANDS_R (H / RB_R)      // 64
#define KSTEPS_R (RB_R + 4)     // 12
#define NBLOCKS_R (NPLANES * BANDS_R * 2 / 4)   // 2048

#define SROW 136            // u32/staged row: [3]=Lhalo [4..131]=data [132]=Rhalo

#define PINF2 0x7C007C00u
#define NINF2 0xFC00FC00u

__device__ __half g_bufA[(size_t)NPLANES * PLANE];   // 32 MB
__device__ __half g_bufB[(size_t)NPLANES * PLANE];   // 32 MB
__device__ double g_acc[4];  // cross_pred, sum_pred, cross_true, sum_true

__device__ __forceinline__ u32 h2min(u32 a, u32 b) {
    __half2 r = __hmin2(*reinterpret_cast<__half2*>(&a),
                        *reinterpret_cast<__half2*>(&b));
    return *reinterpret_cast<u32*>(&r);
}
__device__ __forceinline__ u32 h2max(u32 a, u32 b) {
    __half2 r = __hmax2(*reinterpret_cast<__half2*>(&a),
                        *reinterpret_cast<__half2*>(&b));
    return *reinterpret_cast<u32*>(&r);
}
__device__ __forceinline__ u32 h2sub(u32 a, u32 b) {
    __half2 r = __hsub2(*reinterpret_cast<__half2*>(&a),
                        *reinterpret_cast<__half2*>(&b));
    return *reinterpret_cast<u32*>(&r);
}
__device__ __forceinline__ u32 h2add(u32 a, u32 b) {
    __half2 r = __hadd2(*reinterpret_cast<__half2*>(&a),
                        *reinterpret_cast<__half2*>(&b));
    return *reinterpret_cast<u32*>(&r);
}
__device__ __forceinline__ u32 pk(float lo, float hi) {
    __half2 r = __floats2half2_rn(lo, hi);
    return *reinterpret_cast<u32*>(&r);
}
__device__ __forceinline__ float2 up(u32 v) {
    return __half22float2(*reinterpret_cast<__half2*>(&v));
}
__device__ __forceinline__ u32 mid(u32 a, u32 b) { return __byte_perm(a, b, 0x5432); }
__device__ __forceinline__ u32 swp(u32 a)        { return __byte_perm(a, a, 0x1032); }

// =====================================================================
// Pipeline step (operates on xn[6] = 12 cols: halo +-2 around 8 owned):
// vmin pair -> hmin -> (EDGE row pad) -> hmax -> vmax pair -> z.
// =====================================================================
struct PipeState {
    u32 xprev[6], xpair[6];
    u32 xc1[4], xc2[4], mcp[4];
    u32 hmp[4], hmpair[4];
    __device__ __forceinline__ void init() {
#pragma unroll
        for (int i = 0; i < 6; ++i) { xprev[i] = PINF2; xpair[i] = PINF2; }
#pragma unroll
        for (int i = 0; i < 4; ++i) {
            xc1[i] = 0u; xc2[i] = 0u; mcp[i] = 0u;
            hmp[i] = NINF2; hmpair[i] = NINF2;
        }
    }
};

template <bool EDGE>
__device__ __forceinline__ void pipe_step(
    PipeState& st, const u32 xn[6], int rv, u32 z[4], bool emit)
{
    u32 v[6];
#pragma unroll
    for (int i = 0; i < 6; ++i) v[i] = h2min(st.xpair[i], xn[i]);
#pragma unroll
    for (int i = 0; i < 6; ++i) { st.xpair[i] = h2min(st.xprev[i], xn[i]); st.xprev[i] = xn[i]; }

    u32 p01 = mid(v[0], v[1]), p12 = mid(v[1], v[2]), p23 = mid(v[2], v[3]);
    u32 p34 = mid(v[3], v[4]), p45 = mid(v[4], v[5]);
    u32 m0 = h2min(h2min(swp(v[0]), v[0]), p01);
    u32 m1 = h2min(h2min(p01, v[1]), p12);
    u32 m2 = h2min(h2min(p12, v[2]), p23);
    u32 m3 = h2min(h2min(p23, v[3]), p34);
    u32 m4 = h2min(h2min(p34, v[4]), p45);
    u32 m5 = h2min(h2min(p45, v[5]), swp(v[5]));

    if (EDGE && (unsigned)rv >= H) {     // maxpool pads -inf for OOB rows
        m0 = m1 = m2 = m3 = m4 = m5 = NINF2;
    }

    u32 q01 = mid(m0, m1), q12 = mid(m1, m2), q23 = mid(m2, m3);
    u32 q34 = mid(m3, m4), q45 = mid(m4, m5);
    u32 hv0 = h2max(h2max(q01, m1), q12);
    u32 hv1 = h2max(h2max(q12, m2), q23);
    u32 hv2 = h2max(h2max(q23, m3), q34);
    u32 hv3 = h2max(h2max(q34, m4), q45);

    if (emit) {
        // z = relu(x_o - dil + m_o), dil = max(hmpair, hv)  (dil >= m always)
        z[0] = h2max(h2add(h2sub(st.xc2[0], h2max(st.hmpair[0], hv0)), st.mcp[0]), 0u);
        z[1] = h2max(h2add(h2sub(st.xc2[1], h2max(st.hmpair[1], hv1)), st.mcp[1]), 0u);
        z[2] = h2max(h2add(h2sub(st.xc2[2], h2max(st.hmpair[2], hv2)), st.mcp[2]), 0u);
        z[3] = h2max(h2add(h2sub(st.xc2[3], h2max(st.hmpair[3], hv3)), st.mcp[3]), 0u);
    }

    st.hmpair[0] = h2max(st.hmp[0], hv0); st.hmp[0] = hv0;
    st.hmpair[1] = h2max(st.hmp[1], hv1); st.hmp[1] = hv1;
    st.hmpair[2] = h2max(st.hmp[2], hv2); st.hmp[2] = hv2;
    st.hmpair[3] = h2max(st.hmp[3], hv3); st.hmp[3] = hv3;
    st.mcp[0] = m1; st.mcp[1] = m2; st.mcp[2] = m3; st.mcp[3] = m4;
#pragma unroll
    for (int i = 0; i < 4; ++i) { st.xc2[i] = st.xc1[i]; st.xc1[i] = xn[i + 1]; }
}

// =====================================================================
// Iteration 0: fp32 strided input, register raw-ring + shuffles.
// =====================================================================
template <bool EDGE>
__device__ __forceinline__ void reg_core0(
    int lane, int rbase, int cb, bool eL, bool eR,
    const float* __restrict__ chan, __half* __restrict__ dstH)
{
    u32 raw[4][4];
    u32 rawE[4];
    PipeState st; st.init();

    auto loadraw = [&](int r, int s) {
        u32 a1 = PINF2, a2 = PINF2, a3 = PINF2, a4 = PINF2, ae = PINF2;
        if (!EDGE || (unsigned)r < H) {
            const float* row = chan + (size_t)r * W + cb;
            float4 f0 = *reinterpret_cast<const float4*>(row);
            float4 f1 = *reinterpret_cast<const float4*>(row + 4);
            a1 = pk(f0.x, f0.y); a2 = pk(f0.z, f0.w);
            a3 = pk(f1.x, f1.y); a4 = pk(f1.z, f1.w);
            if (eL)      { float2 e = *reinterpret_cast<const float2*>(row - 2); ae = pk(e.x, e.y); }
            else if (eR) { float2 e = *reinterpret_cast<const float2*>(row + 8); ae = pk(e.x, e.y); }
        }
        raw[s][0] = a1; raw[s][1] = a2; raw[s][2] = a3; raw[s][3] = a4;
        rawE[s] = ae;
    };

    loadraw(rbase - 2, 0);
    loadraw(rbase - 1, 1);

#pragma unroll
    for (int k = 0; k < KSTEPS_R; ++k) {
        if (k < KSTEPS_R - 2) loadraw(rbase + k, (k + 2) & 3);

        u32 xn[6];
        {
            const int s = k & 3;
            u32 a1 = raw[s][0], a4 = raw[s][3];
            u32 a0 = __shfl_up_sync(0xffffffffu, a4, 1);
            u32 a5 = __shfl_down_sync(0xffffffffu, a1, 1);
            if (lane == 0)  a0 = eL ? rawE[s] : PINF2;
            if (lane == 31) a5 = eR ? rawE[s] : PINF2;
            xn[0] = a0; xn[1] = a1; xn[2] = raw[s][1];
            xn[3] = raw[s][2]; xn[4] = a4; xn[5] = a5;
        }

        u32 z[4];
        pipe_step<EDGE>(st, xn, rbase + k - 3, z, k >= 4);
        if (k >= 4) {
            const int o = rbase + k - 4;
            uint4 s4; s4.x = z[0]; s4.y = z[1]; s4.z = z[2]; s4.w = z[3];
            *reinterpret_cast<uint4*>(dstH + (size_t)o * W + cb) = s4;
        }
    }
}

// =====================================================================
// Iterations 1..9: half input staged through per-warp smem ring via
// cp.async (depth-3). Double-buffered consume: slot k+1 is LDS'd during
// step k's compute, so wait_group + LDS latency hide under compute.
// =====================================================================
template <int MODE, bool EDGE>
__device__ __forceinline__ void smem_core(
    u32* __restrict__ swm, int lane, int rbase, int cb, bool eL, bool eR,
    const __half* __restrict__ srcH, __half* __restrict__ dstH,
    const float* __restrict__ oth, float& accC_, float& accS_)
{
    const u32 swa = (u32)__cvta_generic_to_shared(swm);
    PipeState st; st.init();
    float accC = 0.f, accS = 0.f;

    // init halo slots to +inf (boundary strips never overwrite them)
    if (lane < 6) {
        swm[lane * SROW + 3]   = PINF2;
        swm[lane * SROW + 132] = PINF2;
    }
    __syncwarp();

    // slot j holds row rbase-2+j (mod 6)
    auto issue = [&](int j) {
        const int r = rbase - 2 + j;
        const int s = j % 6;
        if (!EDGE || (unsigned)r < H) {
            const __half* row = srcH + (size_t)r * W + cb;
            u32 d = swa + (u32)(s * SROW + 4 + 4 * lane) * 4u;
            asm volatile("cp.async.cg.shared.global [%0], [%1], 16;\n"
                         :: "r"(d), "l"(row));
            if (eL) {
                u32 dh = swa + (u32)(s * SROW + 3) * 4u;
                asm volatile("cp.async.ca.shared.global [%0], [%1], 4;\n"
                             :: "r"(dh), "l"(row - 2));
            } else if (eR) {
                u32 dh = swa + (u32)(s * SROW + 132) * 4u;
                asm volatile("cp.async.ca.shared.global [%0], [%1], 4;\n"
                             :: "r"(dh), "l"(row + 8));
            }
        } else {
            *reinterpret_cast<uint4*>(swm + s * SROW + 4 + 4 * lane) =
                make_uint4(PINF2, PINF2, PINF2, PINF2);
            if (lane == 0)  swm[s * SROW + 3]   = PINF2;
            if (lane == 31) swm[s * SROW + 132] = PINF2;
        }
        asm volatile("cp.async.commit_group;\n" ::);
    };

    auto lds_row = [&](int j, u32 xn[6]) {
        const u32* sb = swm + (j % 6) * SROW + 4 * lane;
        xn[0] = sb[3];
        uint4 c = *reinterpret_cast<const uint4*>(sb + 4);
        xn[1] = c.x; xn[2] = c.y; xn[3] = c.z; xn[4] = c.w;
        xn[5] = sb[8];
    };

    issue(0); issue(1); issue(2); issue(3);      // rows rbase-2 .. rbase+1
    asm volatile("cp.async.wait_group 3;\n" ::); // slot 0 landed
    __syncwarp();
    u32 xn[6];
    lds_row(0, xn);

#pragma unroll
    for (int k = 0; k < KSTEPS_S; ++k) {
        // issue slot k+4 (depth-3 in flight); keep one group per step
        if (k + 4 < KSTEPS_S) issue(k + 4);
        else asm volatile("cp.async.commit_group;\n" ::);
        asm volatile("cp.async.wait_group 3;\n" ::);   // slot k+1 landed
        __syncwarp();

        u32 xn2[6];
        if (k + 1 < KSTEPS_S) lds_row(k + 1, xn2);   // prefetch next row

        u32 z[4];
        pipe_step<EDGE>(st, xn, rbase + k - 3, z, k >= 4);

        if (k >= 4) {
            const int o = rbase + k - 4;
            if (MODE == 2) {
                const float* orow = oth + (size_t)o * W + cb;
                float4 f0 = *reinterpret_cast<const float4*>(orow);
                float4 f1 = *reinterpret_cast<const float4*>(orow + 4);
                float2 a0 = up(z[0]), a1 = up(z[1]), a2 = up(z[2]), a3 = up(z[3]);
                accC += a0.x * f0.x + a0.y * f0.y + a1.x * f0.z + a1.y * f0.w;
                accC += a2.x * f1.x + a2.y * f1.y + a3.x * f1.z + a3.y * f1.w;
                accS += (a0.x + a0.y) + (a1.x + a1.y)
                      + (a2.x + a2.y) + (a3.x + a3.y);
            } else {
                uint4 s4; s4.x = z[0]; s4.y = z[1]; s4.z = z[2]; s4.w = z[3];
                *reinterpret_cast<uint4*>(dstH + (size_t)o * W + cb) = s4;
            }
        }

        if (k + 1 < KSTEPS_S) {
#pragma unroll
            for (int i = 0; i < 6; ++i) xn[i] = xn2[i];
        }
    }

    accC_ = accC;
    accS_ = accS;
}

// =====================================================================
// Kernels
// =====================================================================
__global__ void __launch_bounds__(128) skel0_kernel(
    const float* __restrict__ pred, const float* __restrict__ tru)
{
    // fold accumulator zeroing into iteration 0 (read by MODE2 much later)
    if (blockIdx.x == 0 && threadIdx.x < 4) g_acc[threadIdx.x] = 0.0;

    const int lane  = threadIdx.x & 31;
    const int gw    = blockIdx.x * 4 + (threadIdx.x >> 5);
    const int strip = gw & 1;
    const int band  = (gw >> 1) & (BANDS_R - 1);
    const int p     = gw >> 7;
    const int rbase = band * RB_R;
    const int cb    = strip * 256 + lane * 8;
    const int b     = p & 31;

    const float* chan = (p < 32 ? pred : tru) + (size_t)(2 * b + 1) * PLANE;
    __half* dstH = g_bufA + (size_t)p * PLANE;   // it 0 writes bufA

    const bool eL = (lane == 0  && strip == 1);
    const bool eR = (lane == 31 && strip == 0);

    if (band == 0 || band == BANDS_R - 1)
        reg_core0<true >(lane, rbase, cb, eL, eR, chan, dstH);
    else
        reg_core0<false>(lane, rbase, cb, eL, eR, chan, dstH);
}

template <int MODE>
__global__ void __launch_bounds__(128, 9) skel_kernel(
    const float* __restrict__ pred, const float* __restrict__ tru, int it)
{
    __shared__ __align__(16) u32 stg[4][6 * SROW];   // ~13 KB / block

    const int lane  = threadIdx.x & 31;
    const int wi    = threadIdx.x >> 5;
    const int gw    = blockIdx.x * 4 + wi;
    const int strip = gw & 1;
    const int band  = (gw >> 1) & (BANDS_S - 1);
    const int p     = gw >> 6;
    const int rbase = band * RB_S;
    const int cb    = strip * 256 + lane * 8;
    const int b     = p & 31;

    const float* oth  = (p < 32 ? tru : pred) + (size_t)(2 * b + 1) * PLANE;
    const size_t off  = (size_t)p * PLANE;
    const __half* srcH; __half* dstH;
    if (it & 1) { srcH = g_bufA + off; dstH = g_bufB + off; }
    else        { srcH = g_bufB + off; dstH = g_bufA + off; }

    const bool eL = (lane == 0  && strip == 1);
    const bool eR = (lane == 31 && strip == 0);

    float accC = 0.f, accS = 0.f;
    if (band == 0 || band == BANDS_S - 1)
        smem_core<MODE, true >(stg[wi], lane, rbase, cb, eL, eR, srcH, dstH, oth, accC, accS);
    else
        smem_core<MODE, false>(stg[wi], lane, rbase, cb, eL, eR, srcH, dstH, oth, accC, accS);

    if (MODE == 2) {
#pragma unroll
        for (int s = 16; s; s >>= 1) {
            accC += __shfl_xor_sync(0xffffffffu, accC, s);
            accS += __shfl_xor_sync(0xffffffffu, accS, s);
        }
        __shared__ float sC[4], sS[4];
        if (lane == 0) { sC[wi] = accC; sS[wi] = accS; }
        __syncthreads();
        if (threadIdx.x == 0) {
            double c = (double)sC[0] + sC[1] + sC[2] + sC[3];
            double s = (double)sS[0] + sS[1] + sS[2] + sS[3];
            const int base = (p < 32) ? 0 : 2;   // p constant within block
            atomicAdd(&g_acc[base],     c);
            atomicAdd(&g_acc[base + 1], s);
        }
    }
}

__global__ void finalize_kernel(float* out)
{
    const double SMOOTH = 1.0;
    double tprec = (g_acc[0] + SMOOTH) / (g_acc[1] + SMOOTH);
    double tsens = (g_acc[2] + SMOOTH) / (g_acc[3] + SMOOTH);
    out[0] = (float)(1.0 - 2.0 * (tprec * tsens) / (tprec + tsens));
}

extern "C" void kernel_launch(void* const* d_in, const int* in_sizes, int n_in,
                              void* d_out, int out_size)
{
    const float* pred = (const float*)d_in[0];
    const float* tru  = (const float*)d_in[1];

    skel0_kernel<<<NBLOCKS_R, 128>>>(pred, tru);            // it 0 -> bufA (+acc zero)
    for (int it = 1; it < 9; ++it)
        skel_kernel<1><<<NBLOCKS_S, 128>>>(pred, tru, it);  // ping-pong
    skel_kernel<2><<<NBLOCKS_S, 128>>>(pred, tru, 9);       // + reduction
    finalize_kernel<<<1, 1>>>((float*)d_out);
}